// round 5
// baseline (speedup 1.0000x reference)
#include <cuda_runtime.h>
#include <cuda_fp16.h>

#define B_ 64
#define N_ 1024
#define M_ 1024
#define Q_ 256          // quads per row (float4 / uint2-fp16x4)
#define EPSF 1e-4f
#define NT 128
#define RG 8            // rows per item
#define NG 128          // N_/RG
#define U_ 8            // quads per lane (Q_/32)

__device__ float  g_part[(size_t)B_ * NG * M_];   // per-item column partials
__device__ __half g_h[(size_t)B_ * N_ * M_];      // fp16 copy of s+eps (valid)
__device__ float  g_c[B_ * M_];                   // column factors
__device__ float  g_r[B_ * N_];                   // row factors (per iter)
__device__ unsigned g_ctr[16];
__device__ unsigned g_arrive;
__device__ volatile unsigned g_release;

__device__ __forceinline__ void grid_sync(unsigned nb) {
    __syncthreads();
    if (threadIdx.x == 0) {
        __threadfence();
        unsigned gen = g_release;
        __threadfence();
        if (atomicAdd(&g_arrive, 1) == nb - 1) {
            g_arrive = 0;
            __threadfence();
            g_release = gen + 1;
        } else {
            while (g_release == gen) __nanosleep(64);
        }
    }
    __syncthreads();
}

__device__ __forceinline__ int steal(unsigned* c, int lane) {
    unsigned v = 0;
    if (lane == 0) v = atomicAdd(c, 1u);
    return (int)__shfl_sync(0xffffffffu, v, 0);
}

__device__ __forceinline__ float hdot(uint2 h, float4 c) {
    float2 a = __half22float2(*reinterpret_cast<__half2*>(&h.x));
    float2 d = __half22float2(*reinterpret_cast<__half2*>(&h.y));
    return a.x * c.x + a.y * c.y + d.x * c.z + d.y * c.w;
}

__device__ __forceinline__ int find_b(const int* vpre, int idx) {
    int lo = 0, hi = B_;
    while (hi - lo > 1) {
        int mid = (lo + hi) >> 1;
        if (vpre[mid] <= idx) lo = mid; else hi = mid;
    }
    return lo;
}

// ---------------------------------------------------------------------------
// P0: iter-0 column partials over ALL rows + fp16 copy of s+eps (valid rows).
// ---------------------------------------------------------------------------
__device__ void phase0(const float4* __restrict__ s4,
                       const int* __restrict__ nrows,
                       const int* __restrict__ ncols, int lane) {
    for (;;) {
        int item = steal(&g_ctr[0], lane);
        if (item >= B_ * NG) break;
        int b = item >> 7, rg = item & (NG - 1);
        int nc = __ldg(ncols + b), nr = __ldg(nrows + b);
        int nq = (nc + 3) >> 2;
        const float4* sp = s4 + (size_t)(b * N_ + rg * RG) * Q_;
        uint2* hp = reinterpret_cast<uint2*>(g_h + (size_t)(b * N_ + rg * RG) * M_);
        float4 acc[U_];
#pragma unroll
        for (int u = 0; u < U_; u++) acc[u] = make_float4(0.f, 0.f, 0.f, 0.f);
        for (int r = 0; r < RG; r++) {
            bool wr = (rg * RG + r) < nr;
#pragma unroll
            for (int u = 0; u < U_; u++) {
                int q = lane + 32 * u;
                if (q < nq) {
                    float4 v = __ldg(sp + r * Q_ + q);
                    acc[u].x += v.x; acc[u].y += v.y;
                    acc[u].z += v.z; acc[u].w += v.w;
                    if (wr) {
                        __half2 h0 = __floats2half2_rn(v.x + EPSF, v.y + EPSF);
                        __half2 h1 = __floats2half2_rn(v.z + EPSF, v.w + EPSF);
                        uint2 pk;
                        pk.x = *reinterpret_cast<unsigned*>(&h0);
                        pk.y = *reinterpret_cast<unsigned*>(&h1);
                        hp[r * Q_ + q] = pk;
                    }
                }
            }
        }
        float4* pp = reinterpret_cast<float4*>(g_part) + (size_t)item * Q_;
#pragma unroll
        for (int u = 0; u < U_; u++) __stcg(pp + lane + 32 * u, acc[u]);
    }
}

// ---------------------------------------------------------------------------
// Finalize: c_j = 1/sum(group partials), masked. Deterministic fixed order.
// ---------------------------------------------------------------------------
template <int FIRST>
__device__ void finalize(const int* __restrict__ nrows,
                         const int* __restrict__ ncols,
                         int gtid, int gthreads) {
    for (int t = gtid; t < B_ * M_; t += gthreads) {
        int b = t >> 10, j = t & (M_ - 1);
        int nc = __ldg(ncols + b);
        int G = FIRST ? NG : min(NG, (__ldg(nrows + b) + RG - 1) / RG);
        const float* pp = g_part + (size_t)b * NG * M_ + j;
        float a0 = 0.f, a1 = 0.f, a2 = 0.f, a3 = 0.f;
        int g = 0;
        for (; g + 4 <= G; g += 4) {
            a0 += __ldcg(pp + (size_t)(g + 0) * M_);
            a1 += __ldcg(pp + (size_t)(g + 1) * M_);
            a2 += __ldcg(pp + (size_t)(g + 2) * M_);
            a3 += __ldcg(pp + (size_t)(g + 3) * M_);
        }
        for (; g < G; g++) a0 += __ldcg(pp + (size_t)g * M_);
        float sum = ((a0 + a1) + (a2 + a3)) + (FIRST ? (float)N_ * EPSF : 0.f);
        float cv = (j < nc && sum > 0.f) ? __fdividef(1.f, sum) : 0.f;
        __stcg(&g_c[t], cv);
    }
}

// ---------------------------------------------------------------------------
// Pass A: row sums over fp16 (L2-hit). rinv_i = 1/<h_i, c>. Rows in pairs to
// overlap the two shuffle-reduction chains.
// ---------------------------------------------------------------------------
__device__ void passA(const int* __restrict__ nrows,
                      const int* __restrict__ ncols,
                      int lane, unsigned* ctr, const int* vpre) {
    int count = vpre[B_];
    for (;;) {
        int idx = steal(ctr, lane);
        if (idx >= count) break;
        int b = find_b(vpre, idx), rg = idx - vpre[b];
        int nr = __ldg(nrows + b), nc = __ldg(ncols + b);
        int nq = (nc + 3) >> 2;
        int i0 = rg * RG;
        int rows = min(RG, nr - i0);
        const uint2* hp = reinterpret_cast<const uint2*>(
            g_h + (size_t)(b * N_ + i0) * M_);
        const float4* cp = reinterpret_cast<const float4*>(g_c) + b * Q_;
        float4 c[U_];
#pragma unroll
        for (int u = 0; u < U_; u++) c[u] = __ldcg(cp + lane + 32 * u);
        float* rp = g_r + b * N_ + i0;
        int r = 0;
        for (; r + 2 <= rows; r += 2) {
            float rs0 = 0.f, rs1 = 0.f;
#pragma unroll
            for (int u = 0; u < U_; u++) {
                int q = lane + 32 * u;
                if (q < nq) {
                    rs0 += hdot(__ldg(hp + r * Q_ + q), c[u]);
                    rs1 += hdot(__ldg(hp + (r + 1) * Q_ + q), c[u]);
                }
            }
#pragma unroll
            for (int o = 16; o; o >>= 1) {
                rs0 += __shfl_xor_sync(0xffffffffu, rs0, o);
                rs1 += __shfl_xor_sync(0xffffffffu, rs1, o);
            }
            if (lane == 0) {
                __stcg(rp + r,     rs0 > 0.f ? __fdividef(1.f, rs0) : 0.f);
                __stcg(rp + r + 1, rs1 > 0.f ? __fdividef(1.f, rs1) : 0.f);
            }
        }
        if (r < rows) {
            float rs0 = 0.f;
#pragma unroll
            for (int u = 0; u < U_; u++) {
                int q = lane + 32 * u;
                if (q < nq) rs0 += hdot(__ldg(hp + r * Q_ + q), c[u]);
            }
#pragma unroll
            for (int o = 16; o; o >>= 1)
                rs0 += __shfl_xor_sync(0xffffffffu, rs0, o);
            if (lane == 0)
                __stcg(rp + r, rs0 > 0.f ? __fdividef(1.f, rs0) : 0.f);
        }
    }
}

// ---------------------------------------------------------------------------
// Pass B: column partial accumulate with known rinv. Pure streaming FMA,
// no reductions. acc lives in 32 regs.
// ---------------------------------------------------------------------------
__device__ void passB(const int* __restrict__ nrows,
                      const int* __restrict__ ncols,
                      int lane, unsigned* ctr, const int* vpre) {
    int count = vpre[B_];
    for (;;) {
        int idx = steal(ctr, lane);
        if (idx >= count) break;
        int b = find_b(vpre, idx), rg = idx - vpre[b];
        int nr = __ldg(nrows + b), nc = __ldg(ncols + b);
        int nq = (nc + 3) >> 2;
        int i0 = rg * RG;
        int rows = min(RG, nr - i0);
        const uint2* hp = reinterpret_cast<const uint2*>(
            g_h + (size_t)(b * N_ + i0) * M_);
        const float* rp = g_r + b * N_ + i0;
        float4 acc[U_];
#pragma unroll
        for (int u = 0; u < U_; u++) acc[u] = make_float4(0.f, 0.f, 0.f, 0.f);
        for (int r = 0; r < rows; r++) {
            float rv = __ldcg(rp + r);
#pragma unroll
            for (int u = 0; u < U_; u++) {
                int q = lane + 32 * u;
                if (q < nq) {
                    uint2 h = __ldg(hp + r * Q_ + q);
                    float2 a = __half22float2(*reinterpret_cast<__half2*>(&h.x));
                    float2 d = __half22float2(*reinterpret_cast<__half2*>(&h.y));
                    acc[u].x += a.x * rv; acc[u].y += a.y * rv;
                    acc[u].z += d.x * rv; acc[u].w += d.y * rv;
                }
            }
        }
        float4* pp = reinterpret_cast<float4*>(g_part) +
                     (size_t)(b * NG + rg) * Q_;
#pragma unroll
        for (int u = 0; u < U_; u++) __stcg(pp + lane + 32 * u, acc[u]);
    }
}

// ---------------------------------------------------------------------------
// Final: iter-9 row norm from fp32 s, fused with masked output write.
// ---------------------------------------------------------------------------
__device__ void final_pass(const float4* __restrict__ s4,
                           const int* __restrict__ nrows,
                           const int* __restrict__ ncols,
                           float4* __restrict__ o4, int gw, int tw, int lane) {
    const float4 z = make_float4(0.f, 0.f, 0.f, 0.f);
    for (int item = gw; item < B_ * NG; item += tw) {
        int b = item >> 7, rg = item & (NG - 1);
        int nr = __ldg(nrows + b);
        int i0 = rg * RG;
        float4* op = o4 + (size_t)(b * N_ + i0) * Q_;
        if (i0 >= nr) {
            for (int r = 0; r < RG; r++)
#pragma unroll
                for (int u = 0; u < U_; u++)
                    __stcg(op + r * Q_ + lane + 32 * u, z);
            continue;
        }
        int nc = __ldg(ncols + b);
        int nq = (nc + 3) >> 2;
        const float4* sp = s4 + (size_t)(b * N_ + i0) * Q_;
        const float4* cp = reinterpret_cast<const float4*>(g_c) + b * Q_;
        float4 c[U_];
#pragma unroll
        for (int u = 0; u < U_; u++) c[u] = __ldcg(cp + lane + 32 * u);
        for (int r = 0; r < RG; r++) {
            int i = i0 + r;
            if (i < nr) {
                float rs = 0.f;
#pragma unroll
                for (int u = 0; u < U_; u++) {
                    int q = lane + 32 * u;
                    if (q < nq) {
                        float4 v = __ldg(sp + r * Q_ + q);
                        rs += (v.x + EPSF) * c[u].x + (v.y + EPSF) * c[u].y +
                              (v.z + EPSF) * c[u].z + (v.w + EPSF) * c[u].w;
                    }
                }
#pragma unroll
                for (int o = 16; o; o >>= 1)
                    rs += __shfl_xor_sync(0xffffffffu, rs, o);
                float rinv = rs > 0.f ? __fdividef(1.f, rs) : 0.f;
#pragma unroll
                for (int u = 0; u < U_; u++) {
                    int q = lane + 32 * u;
                    float4 o = z;
                    if (q < nq) {
                        float4 v = __ldg(sp + r * Q_ + q);  // L1 hit
                        o.x = (v.x + EPSF) * rinv * c[u].x;
                        o.y = (v.y + EPSF) * rinv * c[u].y;
                        o.z = (v.z + EPSF) * rinv * c[u].z;
                        o.w = (v.w + EPSF) * rinv * c[u].w;
                    }
                    __stcg(op + r * Q_ + lane + 32 * u, o);
                }
            } else {
#pragma unroll
                for (int u = 0; u < U_; u++)
                    __stcg(op + r * Q_ + lane + 32 * u, z);
            }
        }
    }
}

// ---------------------------------------------------------------------------
__global__ void __launch_bounds__(NT, 6)
sinkhorn_kernel(const float* __restrict__ s, const int* __restrict__ nrows,
                const int* __restrict__ ncols, float* __restrict__ out) {
    __shared__ int vpre[B_ + 1];
    if (threadIdx.x == 0) {
        int a = 0;
        for (int b = 0; b < B_; b++) {
            vpre[b] = a;
            a += (__ldg(nrows + b) + RG - 1) / RG;
        }
        vpre[B_] = a;
    }
    __syncthreads();

    const unsigned nb = gridDim.x;
    const int lane = threadIdx.x & 31;
    const int gw = blockIdx.x * (NT / 32) + (threadIdx.x >> 5);
    const int tw = nb * (NT / 32);
    const int gtid = blockIdx.x * NT + threadIdx.x;
    const int gthreads = nb * NT;
    const float4* s4 = reinterpret_cast<const float4*>(s);
    float4* o4 = reinterpret_cast<float4*>(out);

    phase0(s4, nrows, ncols, lane);            // iter 0 partials + fp16 copy
    grid_sync(nb);
    finalize<1>(nrows, ncols, gtid, gthreads);
    grid_sync(nb);
#pragma unroll 1
    for (int k = 0; k < 4; k++) {              // iters 1..8
        passA(nrows, ncols, lane, &g_ctr[1 + 2 * k], vpre);
        grid_sync(nb);
        passB(nrows, ncols, lane, &g_ctr[2 + 2 * k], vpre);
        grid_sync(nb);
        finalize<0>(nrows, ncols, gtid, gthreads);
        grid_sync(nb);
    }
    // all counter uses are behind the last grid_sync -> safe to reset
    if (blockIdx.x == 0 && threadIdx.x < 16) g_ctr[threadIdx.x] = 0;

    final_pass(s4, nrows, ncols, o4, gw, tw, lane);  // iter 9 + output
}

extern "C" void kernel_launch(void* const* d_in, const int* in_sizes, int n_in,
                              void* d_out, int out_size) {
    const float* s   = (const float*)d_in[0];
    const int* nrows = (const int*)d_in[1];
    const int* ncols = (const int*)d_in[2];
    float* out       = (float*)d_out;

    int dev = 0;
    cudaGetDevice(&dev);
    int sms = 0;
    cudaDeviceGetAttribute(&sms, cudaDevAttrMultiProcessorCount, dev);
    int bpm = 0;
    cudaOccupancyMaxActiveBlocksPerMultiprocessor(&bpm, sinkhorn_kernel, NT, 0);
    int grid = sms * bpm;
    if (grid < 1) grid = 1;

    sinkhorn_kernel<<<grid, NT>>>(s, nrows, ncols, out);
}

// round 7
// speedup vs baseline: 1.1353x; 1.1353x over previous
#include <cuda_runtime.h>
#include <cuda_fp16.h>

#define B_ 64
#define N_ 1024
#define M_ 1024
#define Q_ 256          // quads per row
#define EPSF 1e-4f
#define NT 128
#define RG 8            // rows per item
#define NG 128          // N_/RG
#define U_ 8            // quads per lane (Q_/32)

__device__ float  g_part[(size_t)B_ * NG * M_];   // per-item column partials
__device__ __half g_h[(size_t)B_ * N_ * M_];      // fp16 copy of s+eps (valid)
__device__ float  g_c[B_ * M_];                   // column factors
__device__ unsigned g_ctr[8];
__device__ unsigned g_arrive;
__device__ volatile unsigned g_release;

__device__ __forceinline__ void grid_sync(unsigned nb) {
    __syncthreads();
    if (threadIdx.x == 0) {
        __threadfence();
        unsigned gen = g_release;
        __threadfence();
        if (atomicAdd(&g_arrive, 1) == nb - 1) {
            g_arrive = 0;
            __threadfence();
            g_release = gen + 1;
        } else {
            while (g_release == gen) __nanosleep(64);
        }
    }
    __syncthreads();
}

__device__ __forceinline__ int steal(unsigned* c, int lane) {
    unsigned v = 0;
    if (lane == 0) v = atomicAdd(c, 1u);
    return (int)__shfl_sync(0xffffffffu, v, 0);
}

__device__ __forceinline__ float warp_sum(float v) {
#pragma unroll
    for (int o = 16; o; o >>= 1) v += __shfl_xor_sync(0xffffffffu, v, o);
    return v;
}

// Two independent butterfly chains interleaved -> SHFL latency overlapped.
__device__ __forceinline__ void warp_sum2(float& a, float& b) {
#pragma unroll
    for (int o = 16; o; o >>= 1) {
        a += __shfl_xor_sync(0xffffffffu, a, o);
        b += __shfl_xor_sync(0xffffffffu, b, o);
    }
}

__device__ __forceinline__ float hdot(uint2 h, float4 c) {
    float2 a = __half22float2(*reinterpret_cast<__half2*>(&h.x));
    float2 d = __half22float2(*reinterpret_cast<__half2*>(&h.y));
    return a.x * c.x + a.y * c.y + d.x * c.z + d.y * c.w;
}

__device__ __forceinline__ int find_b(const int* vpre, int idx) {
    int lo = 0, hi = B_;
    while (hi - lo > 1) {
        int mid = (lo + hi) >> 1;
        if (vpre[mid] <= idx) lo = mid; else hi = mid;
    }
    return lo;
}

// ---------------------------------------------------------------------------
// P0: iter-0 column partials over ALL rows + fp16 copy of s+eps (valid rows).
// ---------------------------------------------------------------------------
__device__ void phase0(const float4* __restrict__ s4,
                       const int* __restrict__ nrows,
                       const int* __restrict__ ncols, int lane) {
    for (;;) {
        int item = steal(&g_ctr[0], lane);
        if (item >= B_ * NG) break;
        int b = item >> 7, rg = item & (NG - 1);
        int nc = __ldg(ncols + b), nr = __ldg(nrows + b);
        int nq = (nc + 3) >> 2;
        const float4* sp = s4 + (size_t)(b * N_ + rg * RG) * Q_;
        uint2* hp = reinterpret_cast<uint2*>(g_h + (size_t)(b * N_ + rg * RG) * M_);
        float4 acc[U_];
#pragma unroll
        for (int u = 0; u < U_; u++) acc[u] = make_float4(0.f, 0.f, 0.f, 0.f);
        for (int r = 0; r < RG; r++) {
            bool wr = (rg * RG + r) < nr;
#pragma unroll
            for (int u = 0; u < U_; u++) {
                int q = lane + 32 * u;
                if (q < nq) {
                    float4 v = __ldg(sp + r * Q_ + q);
                    acc[u].x += v.x; acc[u].y += v.y;
                    acc[u].z += v.z; acc[u].w += v.w;
                    if (wr) {
                        __half2 h0 = __floats2half2_rn(v.x + EPSF, v.y + EPSF);
                        __half2 h1 = __floats2half2_rn(v.z + EPSF, v.w + EPSF);
                        uint2 pk;
                        pk.x = *reinterpret_cast<unsigned*>(&h0);
                        pk.y = *reinterpret_cast<unsigned*>(&h1);
                        hp[r * Q_ + q] = pk;
                    }
                }
            }
        }
        float4* pp = reinterpret_cast<float4*>(g_part) + (size_t)item * Q_;
#pragma unroll
        for (int u = 0; u < U_; u++) __stcg(pp + lane + 32 * u, acc[u]);
    }
}

// ---------------------------------------------------------------------------
// Finalize: c_j = 1/sum(group partials), masked. Deterministic fixed order.
// ---------------------------------------------------------------------------
template <int FIRST>
__device__ void finalize(const int* __restrict__ nrows,
                         const int* __restrict__ ncols,
                         int gtid, int gthreads) {
    for (int t = gtid; t < B_ * M_; t += gthreads) {
        int b = t >> 10, j = t & (M_ - 1);
        int nc = __ldg(ncols + b);
        int G = FIRST ? NG : min(NG, (__ldg(nrows + b) + RG - 1) / RG);
        const float* pp = g_part + (size_t)b * NG * M_ + j;
        float a0 = 0.f, a1 = 0.f, a2 = 0.f, a3 = 0.f;
        int g = 0;
        for (; g + 4 <= G; g += 4) {
            a0 += __ldcg(pp + (size_t)(g + 0) * M_);
            a1 += __ldcg(pp + (size_t)(g + 1) * M_);
            a2 += __ldcg(pp + (size_t)(g + 2) * M_);
            a3 += __ldcg(pp + (size_t)(g + 3) * M_);
        }
        for (; g < G; g++) a0 += __ldcg(pp + (size_t)g * M_);
        float sum = ((a0 + a1) + (a2 + a3)) + (FIRST ? (float)N_ * EPSF : 0.f);
        float cv = (j < nc && sum > 0.f) ? __fdividef(1.f, sum) : 0.f;
        __stcg(&g_c[t], cv);
    }
}

// ---------------------------------------------------------------------------
// Fused row+col pass: per warp-item (b, 8 valid rows), pair rows, paired
// shuffle reductions, reload (L1 hit) for the accumulate — no h[] retention.
// ---------------------------------------------------------------------------
__device__ void fused(const int* __restrict__ nrows,
                      const int* __restrict__ ncols,
                      int lane, unsigned* ctr, const int* vpre) {
    int count = vpre[B_];
    for (;;) {
        int idx = steal(ctr, lane);
        if (idx >= count) break;
        int b = find_b(vpre, idx), rg = idx - vpre[b];
        int nr = __ldg(nrows + b), nc = __ldg(ncols + b);
        int nq = (nc + 3) >> 2;
        int i0 = rg * RG;
        int rows = min(RG, nr - i0);
        const uint2* hp = reinterpret_cast<const uint2*>(
            g_h + (size_t)(b * N_ + i0) * M_);
        const float4* cp = reinterpret_cast<const float4*>(g_c) + b * Q_;
        float4 c[U_], acc[U_];
#pragma unroll
        for (int u = 0; u < U_; u++) {
            c[u] = __ldcg(cp + lane + 32 * u);
            acc[u] = make_float4(0.f, 0.f, 0.f, 0.f);
        }
        int r = 0;
        for (; r + 2 <= rows; r += 2) {
            float rs0 = 0.f, rs1 = 0.f;
#pragma unroll
            for (int u = 0; u < U_; u++) {
                int q = lane + 32 * u;
                if (q < nq) {
                    rs0 += hdot(__ldg(hp + r * Q_ + q), c[u]);
                    rs1 += hdot(__ldg(hp + (r + 1) * Q_ + q), c[u]);
                }
            }
            warp_sum2(rs0, rs1);
            float ri0 = rs0 > 0.f ? __fdividef(1.f, rs0) : 0.f;
            float ri1 = rs1 > 0.f ? __fdividef(1.f, rs1) : 0.f;
#pragma unroll
            for (int u = 0; u < U_; u++) {
                int q = lane + 32 * u;
                if (q < nq) {
                    uint2 h0 = __ldg(hp + r * Q_ + q);        // L1 hit
                    uint2 h1 = __ldg(hp + (r + 1) * Q_ + q);  // L1 hit
                    float2 a0 = __half22float2(*reinterpret_cast<__half2*>(&h0.x));
                    float2 d0 = __half22float2(*reinterpret_cast<__half2*>(&h0.y));
                    float2 a1 = __half22float2(*reinterpret_cast<__half2*>(&h1.x));
                    float2 d1 = __half22float2(*reinterpret_cast<__half2*>(&h1.y));
                    acc[u].x += a0.x * ri0 + a1.x * ri1;
                    acc[u].y += a0.y * ri0 + a1.y * ri1;
                    acc[u].z += d0.x * ri0 + d1.x * ri1;
                    acc[u].w += d0.y * ri0 + d1.y * ri1;
                }
            }
        }
        if (r < rows) {
            float rs0 = 0.f;
#pragma unroll
            for (int u = 0; u < U_; u++) {
                int q = lane + 32 * u;
                if (q < nq) rs0 += hdot(__ldg(hp + r * Q_ + q), c[u]);
            }
            rs0 = warp_sum(rs0);
            float ri0 = rs0 > 0.f ? __fdividef(1.f, rs0) : 0.f;
#pragma unroll
            for (int u = 0; u < U_; u++) {
                int q = lane + 32 * u;
                if (q < nq) {
                    uint2 h0 = __ldg(hp + r * Q_ + q);
                    float2 a0 = __half22float2(*reinterpret_cast<__half2*>(&h0.x));
                    float2 d0 = __half22float2(*reinterpret_cast<__half2*>(&h0.y));
                    acc[u].x += a0.x * ri0; acc[u].y += a0.y * ri0;
                    acc[u].z += d0.x * ri0; acc[u].w += d0.y * ri0;
                }
            }
        }
        float4* pp = reinterpret_cast<float4*>(g_part) +
                     (size_t)(b * NG + rg) * Q_;
#pragma unroll
        for (int u = 0; u < U_; u++) __stcg(pp + lane + 32 * u, acc[u]);
    }
}

// ---------------------------------------------------------------------------
// Final: iter-9 row norm from the fp16 copy (L2-resident) + masked output.
// ---------------------------------------------------------------------------
__device__ void final_pass(const int* __restrict__ nrows,
                           const int* __restrict__ ncols,
                           float4* __restrict__ o4, int gw, int tw, int lane) {
    const float4 z = make_float4(0.f, 0.f, 0.f, 0.f);
    for (int item = gw; item < B_ * NG; item += tw) {
        int b = item >> 7, rg = item & (NG - 1);
        int nr = __ldg(nrows + b);
        int i0 = rg * RG;
        float4* op = o4 + (size_t)(b * N_ + i0) * Q_;
        if (i0 >= nr) {
            for (int r = 0; r < RG; r++)
#pragma unroll
                for (int u = 0; u < U_; u++)
                    __stcg(op + r * Q_ + lane + 32 * u, z);
            continue;
        }
        int nc = __ldg(ncols + b);
        int nq = (nc + 3) >> 2;
        int rows = min(RG, nr - i0);
        const uint2* hp = reinterpret_cast<const uint2*>(
            g_h + (size_t)(b * N_ + i0) * M_);
        const float4* cp = reinterpret_cast<const float4*>(g_c) + b * Q_;
        float4 c[U_];
#pragma unroll
        for (int u = 0; u < U_; u++) c[u] = __ldcg(cp + lane + 32 * u);
        for (int r = 0; r < RG; r++) {
            if (r < rows) {
                float rs = 0.f;
#pragma unroll
                for (int u = 0; u < U_; u++) {
                    int q = lane + 32 * u;
                    if (q < nq) rs += hdot(__ldg(hp + r * Q_ + q), c[u]);
                }
                rs = warp_sum(rs);
                float rinv = rs > 0.f ? __fdividef(1.f, rs) : 0.f;
#pragma unroll
                for (int u = 0; u < U_; u++) {
                    int q = lane + 32 * u;
                    float4 o = z;
                    if (q < nq) {
                        uint2 h = __ldg(hp + r * Q_ + q);  // L1 hit
                        float2 a = __half22float2(*reinterpret_cast<__half2*>(&h.x));
                        float2 d = __half22float2(*reinterpret_cast<__half2*>(&h.y));
                        o.x = a.x * rinv * c[u].x;
                        o.y = a.y * rinv * c[u].y;
                        o.z = d.x * rinv * c[u].z;
                        o.w = d.y * rinv * c[u].w;
                    }
                    __stcg(op + r * Q_ + lane + 32 * u, o);
                }
            } else {
#pragma unroll
                for (int u = 0; u < U_; u++)
                    __stcg(op + r * Q_ + lane + 32 * u, z);
            }
        }
    }
}

// ---------------------------------------------------------------------------
__global__ void __launch_bounds__(NT, 6)
sinkhorn_kernel(const float* __restrict__ s, const int* __restrict__ nrows,
                const int* __restrict__ ncols, float* __restrict__ out) {
    __shared__ int vpre[B_ + 1];
    if (threadIdx.x == 0) {
        int a = 0;
        for (int b = 0; b < B_; b++) {
            vpre[b] = a;
            a += (__ldg(nrows + b) + RG - 1) / RG;
        }
        vpre[B_] = a;
    }
    __syncthreads();

    const unsigned nb = gridDim.x;
    const int lane = threadIdx.x & 31;
    const int gw = blockIdx.x * (NT / 32) + (threadIdx.x >> 5);
    const int tw = nb * (NT / 32);
    const int gtid = blockIdx.x * NT + threadIdx.x;
    const int gthreads = nb * NT;
    const float4* s4 = reinterpret_cast<const float4*>(s);
    float4* o4 = reinterpret_cast<float4*>(out);

    phase0(s4, nrows, ncols, lane);            // iter 0 partials + fp16 copy
    grid_sync(nb);
    finalize<1>(nrows, ncols, gtid, gthreads);
    grid_sync(nb);
#pragma unroll 1
    for (int k = 0; k < 4; k++) {              // iters 1..8
        fused(nrows, ncols, lane, &g_ctr[1 + k], vpre);
        grid_sync(nb);
        finalize<0>(nrows, ncols, gtid, gthreads);
        grid_sync(nb);
    }
    // all steal-counter uses are behind the last grid_sync -> safe to reset
    if (blockIdx.x == 0 && threadIdx.x < 8) g_ctr[threadIdx.x] = 0;

    final_pass(nrows, ncols, o4, gw, tw, lane);  // iter 9 + output (fp16 src)
}

extern "C" void kernel_launch(void* const* d_in, const int* in_sizes, int n_in,
                              void* d_out, int out_size) {
    const float* s   = (const float*)d_in[0];
    const int* nrows = (const int*)d_in[1];
    const int* ncols = (const int*)d_in[2];
    float* out       = (float*)d_out;

    int dev = 0;
    cudaGetDevice(&dev);
    int sms = 0;
    cudaDeviceGetAttribute(&sms, cudaDevAttrMultiProcessorCount, dev);
    int bpm = 0;
    cudaOccupancyMaxActiveBlocksPerMultiprocessor(&bpm, sinkhorn_kernel, NT, 0);
    int grid = sms * bpm;
    if (grid < 1) grid = 1;

    sinkhorn_kernel<<<grid, NT>>>(s, nrows, ncols, out);
}

// round 8
// speedup vs baseline: 1.5331x; 1.3504x over previous
#include <cuda_runtime.h>

#define B_ 64
#define N_ 1024
#define M_ 1024
#define Q_ 256          // float4 quads per row
#define QH 128          // quads per half-row
#define EPSF 1e-4f
#define NT 128          // 4 warps = 2 pairs
#define RG 8            // rows per item
#define NG 128          // N_/RG
#define UH 4            // quads per lane per half

__device__ float g_part[(size_t)B_ * NG * M_];
__device__ float g_c[B_ * M_];
__device__ unsigned g_ctr[8];
__device__ unsigned g_arrive;
__device__ volatile unsigned g_release;

__device__ __forceinline__ void grid_sync(unsigned nb) {
    __syncthreads();
    if (threadIdx.x == 0) {
        __threadfence();
        unsigned gen = g_release;
        __threadfence();
        if (atomicAdd(&g_arrive, 1) == nb - 1) {
            g_arrive = 0;
            __threadfence();
            g_release = gen + 1;
        } else {
            while (g_release == gen) __nanosleep(64);
        }
    }
    __syncthreads();
}

__device__ __forceinline__ float warp_sum(float v) {
#pragma unroll
    for (int o = 16; o; o >>= 1) v += __shfl_xor_sync(0xffffffffu, v, o);
    return v;
}
__device__ __forceinline__ void warp_sum2(float& a, float& b) {
#pragma unroll
    for (int o = 16; o; o >>= 1) {
        a += __shfl_xor_sync(0xffffffffu, a, o);
        b += __shfl_xor_sync(0xffffffffu, b, o);
    }
}

// pair barrier: warps {0,1} -> id 1, warps {2,3} -> id 2 (id 0 = __syncthreads)
#define BARP(p) asm volatile("bar.sync %0, 64;" :: "r"(1 + (p)) : "memory")

struct Shm {
    int sb[B_];          // batches sorted by nc descending (LPT)
    int vpre[B_ + 1];    // prefix of valid row-groups over sorted order
    int snr[B_], snc[B_];
    int idx[2];          // per-pair stolen item
    float cs[2][2];      // per-pair csum halves
    float xch[2][2][2][2];  // [pair][buf][half][rowInPair] row-sum exchange
};

// ---------------------------------------------------------------------------
// finalize: c_j = 1/(sum of group partials) masked; skips j>=nc reads.
// ---------------------------------------------------------------------------
__device__ void finalize_phase(const int* snr, const int* snc,
                               int gtid, int gthreads, int first) {
    for (int t = gtid; t < B_ * M_; t += gthreads) {
        int b = t >> 10, j = t & (M_ - 1);
        int nc = snc[b];
        if (j >= nc) { __stcg(&g_c[t], 0.f); continue; }
        int G = first ? NG : min(NG, (snr[b] + RG - 1) / RG);
        const float* pp = g_part + (size_t)b * NG * M_ + j;
        float a0 = 0.f, a1 = 0.f, a2 = 0.f, a3 = 0.f;
        int g = 0;
        for (; g + 4 <= G; g += 4) {
            a0 += __ldcg(pp + (size_t)(g + 0) * M_);
            a1 += __ldcg(pp + (size_t)(g + 1) * M_);
            a2 += __ldcg(pp + (size_t)(g + 2) * M_);
            a3 += __ldcg(pp + (size_t)(g + 3) * M_);
        }
        for (; g < G; g++) a0 += __ldcg(pp + (size_t)g * M_);
        float sum = ((a0 + a1) + (a2 + a3)) + (first ? (float)N_ * EPSF : 0.f);
        __stcg(&g_c[t], sum > 0.f ? __fdividef(1.f, sum) : 0.f);
    }
}

// ---------------------------------------------------------------------------
// Fused row+col pass: pair-cooperative item = (batch, 8 rows), each warp
// owns a column half. Row sums exchanged via double-buffered smem + BARP.
// eps folded: rowsum = dot(v,c) + e*csum ; acc = sum v*rinv + e*sum(rinv).
// ---------------------------------------------------------------------------
__device__ void fused_pass(const float4* __restrict__ s4, Shm* sh,
                           unsigned* ctr, int lane, int pair, int half) {
    const int count = sh->vpre[B_];
    const int qoff = half * QH;
    for (;;) {
        if ((threadIdx.x & 63) == 0) sh->idx[pair] = (int)atomicAdd(ctr, 1u);
        BARP(pair);
        int idx = sh->idx[pair];
        BARP(pair);
        if (idx >= count) break;
        int lo = 0, hi = B_;
        while (hi - lo > 1) {
            int mid = (lo + hi) >> 1;
            if (sh->vpre[mid] <= idx) lo = mid; else hi = mid;
        }
        int b = sh->sb[lo], rg = idx - sh->vpre[lo];
        int nr = sh->snr[b], nc = sh->snc[b];
        int nq = (nc + 3) >> 2;
        int i0 = rg * RG, rows = min(RG, nr - i0);
        const float4* cp = reinterpret_cast<const float4*>(g_c) + b * Q_ + qoff;
        float4 c[UH], acc[UH];
        float csl = 0.f;
#pragma unroll
        for (int u = 0; u < UH; u++) {
            c[u] = make_float4(0.f, 0.f, 0.f, 0.f);
            if (qoff + lane + 32 * u < nq) c[u] = __ldcg(cp + lane + 32 * u);
            acc[u] = make_float4(0.f, 0.f, 0.f, 0.f);
            csl += (c[u].x + c[u].y) + (c[u].z + c[u].w);
        }
        csl = warp_sum(csl);
        if (lane == 0) sh->cs[pair][half] = csl;
        BARP(pair);
        float ecs = EPSF * (sh->cs[pair][0] + sh->cs[pair][1]);
        const float4* sp = s4 + (size_t)(b * N_ + i0) * Q_ + qoff;
        float rsum = 0.f;
        int r = 0;
        for (; r + 2 <= rows; r += 2) {
            int buf = (r >> 1) & 1;
            float4 v0[UH], v1[UH];
            float rs0 = 0.f, rs1 = 0.f;
#pragma unroll
            for (int u = 0; u < UH; u++) {
                v0[u] = make_float4(0.f, 0.f, 0.f, 0.f);
                v1[u] = v0[u];
                if (qoff + lane + 32 * u < nq) {
                    v0[u] = __ldg(sp + r * Q_ + lane + 32 * u);
                    v1[u] = __ldg(sp + (r + 1) * Q_ + lane + 32 * u);
                }
                rs0 += (v0[u].x * c[u].x + v0[u].y * c[u].y) +
                       (v0[u].z * c[u].z + v0[u].w * c[u].w);
                rs1 += (v1[u].x * c[u].x + v1[u].y * c[u].y) +
                       (v1[u].z * c[u].z + v1[u].w * c[u].w);
            }
            warp_sum2(rs0, rs1);
            if (lane == 0) {
                sh->xch[pair][buf][half][0] = rs0;
                sh->xch[pair][buf][half][1] = rs1;
            }
            BARP(pair);
            float t0 = sh->xch[pair][buf][0][0] + sh->xch[pair][buf][1][0] + ecs;
            float t1 = sh->xch[pair][buf][0][1] + sh->xch[pair][buf][1][1] + ecs;
            float ri0 = t0 > 0.f ? __fdividef(1.f, t0) : 0.f;
            float ri1 = t1 > 0.f ? __fdividef(1.f, t1) : 0.f;
            rsum += ri0 + ri1;
#pragma unroll
            for (int u = 0; u < UH; u++) {
                acc[u].x += v0[u].x * ri0 + v1[u].x * ri1;
                acc[u].y += v0[u].y * ri0 + v1[u].y * ri1;
                acc[u].z += v0[u].z * ri0 + v1[u].z * ri1;
                acc[u].w += v0[u].w * ri0 + v1[u].w * ri1;
            }
        }
        if (r < rows) {
            int buf = (r >> 1) & 1;
            float4 v0[UH];
            float rs0 = 0.f;
#pragma unroll
            for (int u = 0; u < UH; u++) {
                v0[u] = make_float4(0.f, 0.f, 0.f, 0.f);
                if (qoff + lane + 32 * u < nq)
                    v0[u] = __ldg(sp + r * Q_ + lane + 32 * u);
                rs0 += (v0[u].x * c[u].x + v0[u].y * c[u].y) +
                       (v0[u].z * c[u].z + v0[u].w * c[u].w);
            }
            rs0 = warp_sum(rs0);
            if (lane == 0) sh->xch[pair][buf][half][0] = rs0;
            BARP(pair);
            float t0 = sh->xch[pair][buf][0][0] + sh->xch[pair][buf][1][0] + ecs;
            float ri0 = t0 > 0.f ? __fdividef(1.f, t0) : 0.f;
            rsum += ri0;
#pragma unroll
            for (int u = 0; u < UH; u++) {
                acc[u].x += v0[u].x * ri0; acc[u].y += v0[u].y * ri0;
                acc[u].z += v0[u].z * ri0; acc[u].w += v0[u].w * ri0;
            }
        }
        float er = EPSF * rsum;
        float4* pp = reinterpret_cast<float4*>(g_part) +
                     (size_t)(b * NG + rg) * Q_ + qoff;
#pragma unroll
        for (int u = 0; u < UH; u++) {
            if (qoff + lane + 32 * u < nq) {
                float4 o;
                o.x = acc[u].x + er; o.y = acc[u].y + er;
                o.z = acc[u].z + er; o.w = acc[u].w + er;
                __stcg(pp + lane + 32 * u, o);
            }
        }
    }
}

// ---------------------------------------------------------------------------
// Final: iter-9 row norm + masked output. Pair-cooperative, work-stolen over
// ALL groups; invalid groups are pure zero-fill (no bars — symmetric per pair).
// ---------------------------------------------------------------------------
__device__ void final_pass(const float4* __restrict__ s4,
                           float4* __restrict__ o4, Shm* sh,
                           int lane, int pair, int half) {
    const int total = B_ * NG;
    const int qoff = half * QH;
    const float4 z = make_float4(0.f, 0.f, 0.f, 0.f);
    for (;;) {
        if ((threadIdx.x & 63) == 0) sh->idx[pair] = (int)atomicAdd(&g_ctr[5], 1u);
        BARP(pair);
        int idx = sh->idx[pair];
        BARP(pair);
        if (idx >= total) break;
        int b = idx >> 7, rg = idx & (NG - 1);
        int nr = sh->snr[b];
        int i0 = rg * RG;
        float4* op = o4 + (size_t)(b * N_ + i0) * Q_ + qoff;
        if (i0 >= nr) {
            for (int r = 0; r < RG; r++)
#pragma unroll
                for (int u = 0; u < UH; u++)
                    __stcg(op + r * Q_ + lane + 32 * u, z);
            continue;
        }
        int nc = sh->snc[b];
        int nq = (nc + 3) >> 2;
        int rows = min(RG, nr - i0);
        const float4* cp = reinterpret_cast<const float4*>(g_c) + b * Q_ + qoff;
        float4 c[UH];
        float csl = 0.f;
#pragma unroll
        for (int u = 0; u < UH; u++) {
            c[u] = z;
            if (qoff + lane + 32 * u < nq) c[u] = __ldcg(cp + lane + 32 * u);
            csl += (c[u].x + c[u].y) + (c[u].z + c[u].w);
        }
        csl = warp_sum(csl);
        if (lane == 0) sh->cs[pair][half] = csl;
        BARP(pair);
        float ecs = EPSF * (sh->cs[pair][0] + sh->cs[pair][1]);
        const float4* sp = s4 + (size_t)(b * N_ + i0) * Q_ + qoff;
        int r = 0;
        for (; r + 2 <= rows; r += 2) {
            int buf = (r >> 1) & 1;
            float4 v0[UH], v1[UH];
            float rs0 = 0.f, rs1 = 0.f;
#pragma unroll
            for (int u = 0; u < UH; u++) {
                v0[u] = z; v1[u] = z;
                if (qoff + lane + 32 * u < nq) {
                    v0[u] = __ldg(sp + r * Q_ + lane + 32 * u);
                    v1[u] = __ldg(sp + (r + 1) * Q_ + lane + 32 * u);
                }
                rs0 += (v0[u].x * c[u].x + v0[u].y * c[u].y) +
                       (v0[u].z * c[u].z + v0[u].w * c[u].w);
                rs1 += (v1[u].x * c[u].x + v1[u].y * c[u].y) +
                       (v1[u].z * c[u].z + v1[u].w * c[u].w);
            }
            warp_sum2(rs0, rs1);
            if (lane == 0) {
                sh->xch[pair][buf][half][0] = rs0;
                sh->xch[pair][buf][half][1] = rs1;
            }
            BARP(pair);
            float t0 = sh->xch[pair][buf][0][0] + sh->xch[pair][buf][1][0] + ecs;
            float t1 = sh->xch[pair][buf][0][1] + sh->xch[pair][buf][1][1] + ecs;
            float ri0 = t0 > 0.f ? __fdividef(1.f, t0) : 0.f;
            float ri1 = t1 > 0.f ? __fdividef(1.f, t1) : 0.f;
#pragma unroll
            for (int u = 0; u < UH; u++) {
                float4 o0, o1;
                o0.x = (v0[u].x + EPSF) * ri0 * c[u].x;  // c==0 past nc -> 0
                o0.y = (v0[u].y + EPSF) * ri0 * c[u].y;
                o0.z = (v0[u].z + EPSF) * ri0 * c[u].z;
                o0.w = (v0[u].w + EPSF) * ri0 * c[u].w;
                o1.x = (v1[u].x + EPSF) * ri1 * c[u].x;
                o1.y = (v1[u].y + EPSF) * ri1 * c[u].y;
                o1.z = (v1[u].z + EPSF) * ri1 * c[u].z;
                o1.w = (v1[u].w + EPSF) * ri1 * c[u].w;
                __stcg(op + r * Q_ + lane + 32 * u, o0);
                __stcg(op + (r + 1) * Q_ + lane + 32 * u, o1);
            }
        }
        if (r < rows) {
            int buf = (r >> 1) & 1;
            float4 v0[UH];
            float rs0 = 0.f;
#pragma unroll
            for (int u = 0; u < UH; u++) {
                v0[u] = z;
                if (qoff + lane + 32 * u < nq)
                    v0[u] = __ldg(sp + r * Q_ + lane + 32 * u);
                rs0 += (v0[u].x * c[u].x + v0[u].y * c[u].y) +
                       (v0[u].z * c[u].z + v0[u].w * c[u].w);
            }
            rs0 = warp_sum(rs0);
            if (lane == 0) sh->xch[pair][buf][half][0] = rs0;
            BARP(pair);
            float t0 = sh->xch[pair][buf][0][0] + sh->xch[pair][buf][1][0] + ecs;
            float ri0 = t0 > 0.f ? __fdividef(1.f, t0) : 0.f;
#pragma unroll
            for (int u = 0; u < UH; u++) {
                float4 o0;
                o0.x = (v0[u].x + EPSF) * ri0 * c[u].x;
                o0.y = (v0[u].y + EPSF) * ri0 * c[u].y;
                o0.z = (v0[u].z + EPSF) * ri0 * c[u].z;
                o0.w = (v0[u].w + EPSF) * ri0 * c[u].w;
                __stcg(op + r * Q_ + lane + 32 * u, o0);
            }
        }
        for (int rr = rows; rr < RG; rr++)
#pragma unroll
            for (int u = 0; u < UH; u++)
                __stcg(op + rr * Q_ + lane + 32 * u, z);
    }
}

// ---------------------------------------------------------------------------
__global__ void __launch_bounds__(NT, 5)
sinkhorn_kernel(const float* __restrict__ s, const int* __restrict__ nrows,
                const int* __restrict__ ncols, float* __restrict__ out) {
    __shared__ Shm shm;
    const int tid = threadIdx.x;
    const int lane = tid & 31;
    const int pair = tid >> 6;
    const int half = (tid >> 5) & 1;
    const unsigned nb = gridDim.x;

    if (tid < B_) {
        shm.snr[tid] = __ldg(nrows + tid);
        shm.snc[tid] = __ldg(ncols + tid);
    }
    __syncthreads();
    if (tid < B_) {                      // parallel rank sort by nc desc (LPT)
        int myc = shm.snc[tid];
        int rank = 0;
        for (int j = 0; j < B_; j++) {
            int cj = shm.snc[j];
            rank += (cj > myc) || (cj == myc && j < tid);
        }
        shm.sb[rank] = tid;
    }
    __syncthreads();
    if (tid <= B_) {                     // prefix of valid groups, sorted order
        int a = 0;
        for (int k = 0; k < tid; k++)
            a += (shm.snr[shm.sb[k]] + RG - 1) / RG;
        shm.vpre[tid] = a;
    }
    __syncthreads();

    const float4* s4 = reinterpret_cast<const float4*>(s);
    float4* o4 = reinterpret_cast<float4*>(out);
    const int gtid = blockIdx.x * NT + tid;
    const int gthreads = nb * NT;

    // ---- phase 0: iter-0 column partials (all rows, valid cols) ----
    // per-warp items: (sorted batch, row-group, col-half)
    for (;;) {
        unsigned sv = 0;
        if (lane == 0) sv = atomicAdd(&g_ctr[0], 1u);
        int item = (int)__shfl_sync(0xffffffffu, sv, 0);
        if (item >= B_ * NG * 2) break;
        int b = shm.sb[item >> 8];
        int rem = item & 255;
        int rg = rem >> 1, hf = rem & 1;
        int nq = (shm.snc[b] + 3) >> 2;
        int qoff = hf * QH;
        if (qoff >= nq) continue;
        const float4* sp = s4 + (size_t)(b * N_ + rg * RG) * Q_ + qoff;
        float4 acc[UH];
#pragma unroll
        for (int u = 0; u < UH; u++) acc[u] = make_float4(0.f, 0.f, 0.f, 0.f);
        for (int r = 0; r < RG; r++) {
#pragma unroll
            for (int u = 0; u < UH; u++) {
                if (qoff + lane + 32 * u < nq) {
                    float4 v = __ldg(sp + r * Q_ + lane + 32 * u);
                    acc[u].x += v.x; acc[u].y += v.y;
                    acc[u].z += v.z; acc[u].w += v.w;
                }
            }
        }
        float4* pp = reinterpret_cast<float4*>(g_part) +
                     (size_t)(b * NG + rg) * Q_ + qoff;
#pragma unroll
        for (int u = 0; u < UH; u++)
            if (qoff + lane + 32 * u < nq) __stcg(pp + lane + 32 * u, acc[u]);
    }
    grid_sync(nb);

    finalize_phase(shm.snr, shm.snc, gtid, gthreads, 1);
    // safe reset point: phase0's counter done; fused/final counters (stale
    // from previous replay) not yet in use; grid_sync fences both sides.
    if (blockIdx.x == 0 && tid < 8) g_ctr[tid] = 0;
    grid_sync(nb);

#pragma unroll 1
    for (int k = 0; k < 4; k++) {        // iters 1..8
        fused_pass(s4, &shm, &g_ctr[1 + k], lane, pair, half);
        grid_sync(nb);
        finalize_phase(shm.snr, shm.snc, gtid, gthreads, 0);
        grid_sync(nb);
    }

    final_pass(s4, o4, &shm, lane, pair, half);  // iter 9 + output
}

extern "C" void kernel_launch(void* const* d_in, const int* in_sizes, int n_in,
                              void* d_out, int out_size) {
    const float* s   = (const float*)d_in[0];
    const int* nrows = (const int*)d_in[1];
    const int* ncols = (const int*)d_in[2];
    float* out       = (float*)d_out;

    int dev = 0;
    cudaGetDevice(&dev);
    int sms = 0;
    cudaDeviceGetAttribute(&sms, cudaDevAttrMultiProcessorCount, dev);
    int bpm = 0;
    cudaOccupancyMaxActiveBlocksPerMultiprocessor(&bpm, sinkhorn_kernel, NT, 0);
    int grid = sms * bpm;
    if (grid < 1) grid = 1;

    sinkhorn_kernel<<<grid, NT>>>(s, nrows, ncols, out);
}